// round 11
// baseline (speedup 1.0000x reference)
#include <cuda_runtime.h>
#include <cuda_fp16.h>
#include <cstdint>

#define NB      1024
#define NNODES  10
#define FIN     2048
#define FOUT    128
#define NHEADS  8
#define MTOT    (NB * NNODES)     // 10240
#define KSPLIT  4
#define KCHUNK  (FIN / KSPLIT)    // 512
#define GB      2
#define ROWS_U  (GB * NNODES)     // 20 used rows per fused CTA

// Scratch (allocation-guard-safe __device__ globals)
__device__ float  g_part[KSPLIT][MTOT * FOUT];   // 21 MB split-K partials
__device__ float  g_emb[(MTOT + 64) * FOUT];     // 5.2 MB (+pad rows for fused tile overrun)
__device__ __half g_WpTh[FOUT * FIN];            // Wp^T  [n=128][k=2048], half
__device__ __half g_W1Th[16][FOUT * FOUT];       // W1^T  [z][f=128][k=128], half

// ---------------------------------------------------------------------------
// helpers
// ---------------------------------------------------------------------------
__device__ __forceinline__ uint32_t smem_u32(const void* p) {
    return (uint32_t)__cvta_generic_to_shared(p);
}
__device__ __forceinline__ uint4 f8_to_h8(float4 a, float4 b) {
    __half2 h0 = __float22half2_rn(make_float2(a.x, a.y));
    __half2 h1 = __float22half2_rn(make_float2(a.z, a.w));
    __half2 h2 = __float22half2_rn(make_float2(b.x, b.y));
    __half2 h3 = __float22half2_rn(make_float2(b.z, b.w));
    uint4 r;
    r.x = *(uint32_t*)&h0; r.y = *(uint32_t*)&h1;
    r.z = *(uint32_t*)&h2; r.w = *(uint32_t*)&h3;
    return r;
}
__device__ __forceinline__ void mma16816(float* c, const uint32_t* a,
                                         uint32_t b0, uint32_t b1) {
    asm volatile(
        "mma.sync.aligned.m16n8k16.row.col.f32.f16.f16.f32 "
        "{%0,%1,%2,%3}, {%4,%5,%6,%7}, {%8,%9}, {%0,%1,%2,%3};"
        : "+f"(c[0]), "+f"(c[1]), "+f"(c[2]), "+f"(c[3])
        : "r"(a[0]), "r"(a[1]), "r"(a[2]), "r"(a[3]), "r"(b0), "r"(b1));
}
#define LDMX4(r0, r1, r2, r3, addr) \
    asm volatile("ldmatrix.sync.aligned.m8n8.x4.shared.b16 {%0,%1,%2,%3}, [%4];" \
        : "=r"(r0), "=r"(r1), "=r"(r2), "=r"(r3) : "r"(addr))

// ---------------------------------------------------------------------------
// FP16 MMA GEMM core (R10, proven): C[m0:m0+32][0:128] (+bias) = A(f32) @ Bh^T
// ---------------------------------------------------------------------------
template <int NCH>
__device__ __forceinline__ void gemm_fp16(const float* __restrict__ Ag, int lda,
                                          const __half* __restrict__ Bh, int ldb,
                                          int k0base, int m0,
                                          const float* __restrict__ bias,
                                          float* __restrict__ Cg) {
    __shared__ __align__(16) __half As[32 * 40];     // 2.5 KB
    __shared__ __align__(16) __half Bs[128 * 40];    // 10 KB

    const int tid  = threadIdx.x;
    const int lane = tid & 31;
    const int warp = tid >> 5;
    const int g    = lane >> 2;
    const int t    = lane & 3;

    const int fr  = tid >> 2;
    const int fc8 = (tid & 3) * 8;

    const int a_row  = (lane & 7) + ((lane >> 3) & 1) * 8;
    const int a_koff = ((lane >> 4) & 1) * 8;
    const int b_row  = (lane & 7) + ((lane >> 4) & 1) * 8;
    const int b_koff = ((lane >> 3) & 1) * 8;

    float4 pa0, pa1;
    uint4  pb[4];

    auto loadAB = [&](int k0) {
        const float* p = Ag + (size_t)(m0 + fr) * lda + k0 + fc8;
        pa0 = *(const float4*)p;
        pa1 = *(const float4*)(p + 4);
#pragma unroll
        for (int i = 0; i < 4; i++) {
            int e = tid + 128 * i;
            int r = e >> 2, c8 = (e & 3) * 8;
            pb[i] = *(const uint4*)(Bh + (size_t)r * ldb + k0 + c8);
        }
    };
    auto stsAB = [&]() {
        *(uint4*)(As + fr * 40 + fc8) = f8_to_h8(pa0, pa1);
#pragma unroll
        for (int i = 0; i < 4; i++) {
            int e = tid + 128 * i;
            int r = e >> 2, c8 = (e & 3) * 8;
            *(uint4*)(Bs + r * 40 + c8) = pb[i];
        }
    };

    float acc[2][4][4];
#pragma unroll
    for (int mt = 0; mt < 2; mt++)
#pragma unroll
        for (int nt = 0; nt < 4; nt++)
#pragma unroll
            for (int q = 0; q < 4; q++) acc[mt][nt][q] = 0.f;

    auto compute = [&]() {
#pragma unroll
        for (int ks = 0; ks < 2; ks++) {
            uint32_t a[2][4];
#pragma unroll
            for (int mt = 0; mt < 2; mt++) {
                uint32_t addr = smem_u32(As + (mt * 16 + a_row) * 40 + ks * 16 + a_koff);
                LDMX4(a[mt][0], a[mt][1], a[mt][2], a[mt][3], addr);
            }
#pragma unroll
            for (int nt2 = 0; nt2 < 2; nt2++) {
                uint32_t b[4];
                uint32_t addr = smem_u32(Bs + (warp * 32 + nt2 * 16 + b_row) * 40
                                            + ks * 16 + b_koff);
                LDMX4(b[0], b[1], b[2], b[3], addr);
#pragma unroll
                for (int sub = 0; sub < 2; sub++)
#pragma unroll
                    for (int mt = 0; mt < 2; mt++)
                        mma16816(acc[mt][nt2 * 2 + sub], a[mt],
                                 b[sub * 2], b[sub * 2 + 1]);
            }
        }
    };

    loadAB(k0base);
    stsAB();
    __syncthreads();
    for (int ch = 1; ch < NCH; ch++) {
        loadAB(k0base + ch * 32);
        compute();
        __syncthreads();
        stsAB();
        __syncthreads();
    }
    compute();

#pragma unroll
    for (int mt = 0; mt < 2; mt++) {
#pragma unroll
        for (int nt = 0; nt < 4; nt++) {
            int col = warp * 32 + nt * 8 + 2 * t;
            float bb0 = bias ? bias[col] : 0.f;
            float bb1 = bias ? bias[col + 1] : 0.f;
            int row = m0 + mt * 16 + g;
            *(float2*)(Cg + (size_t)row * FOUT + col) =
                make_float2(acc[mt][nt][0] + bb0, acc[mt][nt][1] + bb1);
            *(float2*)(Cg + (size_t)(row + 8) * FOUT + col) =
                make_float2(acc[mt][nt][2] + bb0, acc[mt][nt][3] + bb1);
        }
    }
}

// ---------------------------------------------------------------------------
// K0a/K0b: weight transposes to half (unchanged from R10)
// ---------------------------------------------------------------------------
__global__ __launch_bounds__(256) void k_trWp(const float* __restrict__ Wp) {
    __shared__ float tb[32][33];
    const int k0 = blockIdx.x * 32, n0 = blockIdx.y * 32;
    const int tx = threadIdx.x & 31, ty0 = threadIdx.x >> 5;
#pragma unroll
    for (int dy = 0; dy < 32; dy += 8)
        tb[ty0 + dy][tx] = Wp[(size_t)(k0 + ty0 + dy) * FOUT + n0 + tx];
    __syncthreads();
#pragma unroll
    for (int dy = 0; dy < 32; dy += 8)
        g_WpTh[(size_t)(n0 + ty0 + dy) * FIN + k0 + tx] = __float2half_rn(tb[tx][ty0 + dy]);
}

__global__ __launch_bounds__(256) void k_trW1(const float* __restrict__ W1) {
    __shared__ float tb[32][33];
    const int z  = blockIdx.z;
    const int k0 = blockIdx.x * 32, f0 = blockIdx.y * 32;
    const int tx = threadIdx.x & 31, ty0 = threadIdx.x >> 5;
    const float* src = W1 + ((size_t)(z >> 1) * 2 * FOUT + (z & 1) * FOUT) * FOUT;
#pragma unroll
    for (int dy = 0; dy < 32; dy += 8)
        tb[ty0 + dy][tx] = src[(size_t)(k0 + ty0 + dy) * FOUT + f0 + tx];
    __syncthreads();
#pragma unroll
    for (int dy = 0; dy < 32; dy += 8)
        g_W1Th[z][(size_t)(f0 + ty0 + dy) * FOUT + k0 + tx] = __float2half_rn(tb[tx][ty0 + dy]);
}

// ---------------------------------------------------------------------------
// K1 + K1b: emb = x @ Wp + bp (split-K fp16 MMA + reduce)   (unchanged, passing)
// ---------------------------------------------------------------------------
__global__ __launch_bounds__(128) void k_emb(const float* __restrict__ x) {
    gemm_fp16<KCHUNK / 32>(x, FIN, g_WpTh, FIN, blockIdx.y * KCHUNK,
                           blockIdx.x * 32, nullptr, g_part[blockIdx.y]);
}

__global__ __launch_bounds__(256) void k_reduce4(const float* __restrict__ bp) {
    const int i = (blockIdx.x * 256 + threadIdx.x) * 4;
    float4 s = *(const float4*)(g_part[0] + i);
#pragma unroll
    for (int p = 1; p < KSPLIT; p++) {
        float4 v = *(const float4*)(g_part[p] + i);
        s.x += v.x; s.y += v.y; s.z += v.z; s.w += v.w;
    }
    float4 bv = *(const float4*)(bp + (i & 127));
    s.x += bv.x; s.y += bv.y; s.z += bv.z; s.w += bv.w;
    *(float4*)(g_emb + i) = s;
}

// ---------------------------------------------------------------------------
// K2 (fused proj+pair): per (batch-pair bg, head h):
//   As <- emb rows [m0, m0+32) as half, full K=128 (stride 136, conflict-free)
//   half 0: Aout[r][f] = (emb @ W1Th[2h]^T)[r][f] + b1[h][f]   (rows r<20)
//   half 1: Cout[r][f] = (emb @ W1Th[2h+1]^T)[r][f]
//   S(i,k) = sum_f leaky(Aout[i][f]+Cout[k][f]) * W2[h][f] + b2[h]
//   out[b,h,j,i] = S(i, j+(j>=i)) for j<9; row 9 zeroed.
// smem: As 8.7K + Bs 10K + Aout 10.3K + Cout 10.3K = 39.3KB. 128 threads.
// ---------------------------------------------------------------------------
__global__ __launch_bounds__(128) void k_fuse(const float* __restrict__ b1,
                                              const float* __restrict__ W2,
                                              const float* __restrict__ b2,
                                              float* __restrict__ out) {
    __shared__ __align__(16) __half As[32 * 136];       // full K=128 + pad 8
    __shared__ __align__(16) __half Bs[128 * 40];
    __shared__ __align__(16) float  Aout[ROWS_U * 132];
    __shared__ __align__(16) float  Cout[ROWS_U * 132];

    const int tid  = threadIdx.x;
    const int lane = tid & 31;
    const int warp = tid >> 5;
    const int g    = lane >> 2;
    const int t    = lane & 3;

    const int m0 = blockIdx.x * ROWS_U;
    const int h  = blockIdx.y;

    const int a_row  = (lane & 7) + ((lane >> 3) & 1) * 8;
    const int a_koff = ((lane >> 4) & 1) * 8;
    const int b_row  = (lane & 7) + ((lane >> 4) & 1) * 8;
    const int b_koff = ((lane >> 3) & 1) * 8;

    // fill As: 32 rows x 128 halves (512 uint4 -> 4/thread), f32->half
#pragma unroll
    for (int i = 0; i < 4; i++) {
        int e = tid + 128 * i;
        int r = e >> 4, c = (e & 15) * 8;
        const float* p = g_emb + (size_t)(m0 + r) * FOUT + c;
        float4 v0 = *(const float4*)p;
        float4 v1 = *(const float4*)(p + 4);
        *(uint4*)(As + r * 136 + c) = f8_to_h8(v0, v1);
    }

    uint4 pb[4];
    const __half* Bsrc;
    auto loadB = [&](int k0) {
#pragma unroll
        for (int i = 0; i < 4; i++) {
            int e = tid + 128 * i;
            int r = e >> 2, c8 = (e & 3) * 8;
            pb[i] = *(const uint4*)(Bsrc + (size_t)r * FOUT + k0 + c8);
        }
    };
    auto stsB = [&]() {
#pragma unroll
        for (int i = 0; i < 4; i++) {
            int e = tid + 128 * i;
            int r = e >> 2, c8 = (e & 3) * 8;
            *(uint4*)(Bs + r * 40 + c8) = pb[i];
        }
    };

    float acc[2][4][4];
    auto zero_acc = [&]() {
#pragma unroll
        for (int mt = 0; mt < 2; mt++)
#pragma unroll
            for (int nt = 0; nt < 4; nt++)
#pragma unroll
                for (int q = 0; q < 4; q++) acc[mt][nt][q] = 0.f;
    };
    auto compute = [&](int ch) {
#pragma unroll
        for (int ks = 0; ks < 2; ks++) {
            uint32_t a[2][4];
#pragma unroll
            for (int mt = 0; mt < 2; mt++) {
                uint32_t addr = smem_u32(As + (mt * 16 + a_row) * 136
                                            + ch * 32 + ks * 16 + a_koff);
                LDMX4(a[mt][0], a[mt][1], a[mt][2], a[mt][3], addr);
            }
#pragma unroll
            for (int nt2 = 0; nt2 < 2; nt2++) {
                uint32_t b[4];
                uint32_t addr = smem_u32(Bs + (warp * 32 + nt2 * 16 + b_row) * 40
                                            + ks * 16 + b_koff);
                LDMX4(b[0], b[1], b[2], b[3], addr);
#pragma unroll
                for (int sub = 0; sub < 2; sub++)
#pragma unroll
                    for (int mt = 0; mt < 2; mt++)
                        mma16816(acc[mt][nt2 * 2 + sub], a[mt],
                                 b[sub * 2], b[sub * 2 + 1]);
            }
        }
    };

    for (int half = 0; half < 2; half++) {
        Bsrc = g_W1Th[2 * h + half];
        zero_acc();
        loadB(0);
        __syncthreads();     // As fill (half 0) / prior Bs reads (half 1) complete
        stsB();
        __syncthreads();
#pragma unroll
        for (int ch = 1; ch < 4; ch++) {
            loadB(ch * 32);
            compute(ch - 1);
            __syncthreads();
            stsB();
            __syncthreads();
        }
        compute(3);

        float* dst = (half == 0) ? Aout : Cout;
#pragma unroll
        for (int mt = 0; mt < 2; mt++) {
#pragma unroll
            for (int nt = 0; nt < 4; nt++) {
                int col = warp * 32 + nt * 8 + 2 * t;
                float bb0 = 0.f, bb1 = 0.f;
                if (half == 0) {
                    bb0 = b1[h * FOUT + col];
                    bb1 = b1[h * FOUT + col + 1];
                }
                int row = mt * 16 + g;
                if (row < ROWS_U)
                    *(float2*)(dst + row * 132 + col) =
                        make_float2(acc[mt][nt][0] + bb0, acc[mt][nt][1] + bb1);
                if (row + 8 < ROWS_U)
                    *(float2*)(dst + (row + 8) * 132 + col) =
                        make_float2(acc[mt][nt][2] + bb0, acc[mt][nt][3] + bb1);
            }
        }
    }
    __syncthreads();

    // ---- pair scoring: GB*90 = 180 pairs, f-split 8 lanes/pair, 4 pairs/warp ----
    const int sub = lane >> 3;
    const int fl  = lane & 7;
    float4 w2v[4];
#pragma unroll
    for (int j = 0; j < 4; j++) w2v[j] = *(const float4*)(W2 + h * FOUT + fl * 16 + j * 4);
    const float b2v = b2[h];
    const int   bb  = blockIdx.x * GB;

    for (int q = warp; q < 45; q += 4) {        // 45 groups of 4 cover 180
        const int p = q * 4 + sub;
        int lb = p / 90, pp = p - lb * 90;
        int i  = pp / 9;
        int kk = pp - i * 9;                    // output row j
        int k  = kk + (kk >= i);                // source node
        const float* ar = Aout + (lb * NNODES + i) * 132 + fl * 16;
        const float* cr = Cout + (lb * NNODES + k) * 132 + fl * 16;
        float s = 0.f;
#pragma unroll
        for (int j = 0; j < 4; j++) {
            float4 av = *(const float4*)(ar + j * 4);
            float4 cv = *(const float4*)(cr + j * 4);
            float v0 = av.x + cv.x, v1 = av.y + cv.y;
            float v2 = av.z + cv.z, v3 = av.w + cv.w;
            v0 = (v0 > 0.f) ? v0 : 0.2f * v0;
            v1 = (v1 > 0.f) ? v1 : 0.2f * v1;
            v2 = (v2 > 0.f) ? v2 : 0.2f * v2;
            v3 = (v3 > 0.f) ? v3 : 0.2f * v3;
            s += v0 * w2v[j].x + v1 * w2v[j].y + v2 * w2v[j].z + v3 * w2v[j].w;
        }
        s += __shfl_xor_sync(0xffffffffu, s, 4);
        s += __shfl_xor_sync(0xffffffffu, s, 2);
        s += __shfl_xor_sync(0xffffffffu, s, 1);
        if (fl == 0)
            out[((size_t)(bb + lb) * NHEADS + h) * 100 + kk * 10 + i] = s + b2v;
    }
    if (tid < GB * 10) {
        int lb = tid / 10, ii = tid - lb * 10;
        out[((size_t)(bb + lb) * NHEADS + h) * 100 + 90 + ii] = 0.f;
    }
}

// ---------------------------------------------------------------------------
// Launch. inputs: 0 object_features, 1 scene_geometry(unused), 2 Wp, 3 bp,
//                 4 W1, 5 b1, 6 W2, 7 b2, 8 d_max
// ---------------------------------------------------------------------------
extern "C" void kernel_launch(void* const* d_in, const int* in_sizes, int n_in,
                              void* d_out, int out_size) {
    const float* x  = (const float*)d_in[0];
    const float* Wp = (const float*)d_in[2];
    const float* bp = (const float*)d_in[3];
    const float* W1 = (const float*)d_in[4];
    const float* b1 = (const float*)d_in[5];
    const float* W2 = (const float*)d_in[6];
    const float* b2 = (const float*)d_in[7];
    float* out = (float*)d_out;

    dim3 gtw(FIN / 32, FOUT / 32);
    k_trWp<<<gtw, 256>>>(Wp);
    dim3 gt1(FOUT / 32, FOUT / 32, 16);
    k_trW1<<<gt1, 256>>>(W1);

    dim3 g1(MTOT / 32, KSPLIT);
    k_emb<<<g1, 128>>>(x);

    k_reduce4<<<MTOT * FOUT / (256 * 4), 256>>>(bp);

    dim3 g2(NB / GB, NHEADS);
    k_fuse<<<g2, 128>>>(b1, W2, b2, out);
}

// round 12
// speedup vs baseline: 1.1092x; 1.1092x over previous
#include <cuda_runtime.h>
#include <cuda_fp16.h>
#include <cstdint>

#define NB      1024
#define NNODES  10
#define FIN     2048
#define FOUT    128
#define NHEADS  8
#define MTOT    (NB * NNODES)     // 10240
#define KSPLIT  4
#define KCHUNK  (FIN / KSPLIT)    // 512

// Scratch (allocation-guard-safe __device__ globals)
__device__ float  g_part[KSPLIT][MTOT * FOUT];   // 21 MB split-K partials
__device__ float  g_emb[MTOT * FOUT];            // 5.2 MB
__device__ float  g_AC[16][MTOT * FOUT];         // 84 MB: [z][m][f], z = 2h+half
__device__ __half g_WpTh[FOUT * FIN];            // Wp^T  [n=128][k=2048], half
__device__ __half g_W1Th[16][FOUT * FOUT];       // W1^T  [z][f=128][k=128], half

// ---------------------------------------------------------------------------
// helpers
// ---------------------------------------------------------------------------
__device__ __forceinline__ uint32_t smem_u32(const void* p) {
    return (uint32_t)__cvta_generic_to_shared(p);
}
__device__ __forceinline__ uint4 f8_to_h8(float4 a, float4 b) {
    __half2 h0 = __float22half2_rn(make_float2(a.x, a.y));
    __half2 h1 = __float22half2_rn(make_float2(a.z, a.w));
    __half2 h2 = __float22half2_rn(make_float2(b.x, b.y));
    __half2 h3 = __float22half2_rn(make_float2(b.z, b.w));
    uint4 r;
    r.x = *(uint32_t*)&h0; r.y = *(uint32_t*)&h1;
    r.z = *(uint32_t*)&h2; r.w = *(uint32_t*)&h3;
    return r;
}
__device__ __forceinline__ void mma16816(float* c, const uint32_t* a,
                                         uint32_t b0, uint32_t b1) {
    asm volatile(
        "mma.sync.aligned.m16n8k16.row.col.f32.f16.f16.f32 "
        "{%0,%1,%2,%3}, {%4,%5,%6,%7}, {%8,%9}, {%0,%1,%2,%3};"
        : "+f"(c[0]), "+f"(c[1]), "+f"(c[2]), "+f"(c[3])
        : "r"(a[0]), "r"(a[1]), "r"(a[2]), "r"(a[3]), "r"(b0), "r"(b1));
}
#define LDMX4(r0, r1, r2, r3, addr) \
    asm volatile("ldmatrix.sync.aligned.m8n8.x4.shared.b16 {%0,%1,%2,%3}, [%4];" \
        : "=r"(r0), "=r"(r1), "=r"(r2), "=r"(r3) : "r"(addr))

// ---------------------------------------------------------------------------
// FP16 MMA GEMM core v2: C[m0:m0+64][0:128] (+bias) = A(f32)[m0:][k-span] @ Bh^T
// 256 threads, 8 warps (2 m-groups x 4 n-groups), warptile 32x32 (fragment
// maps identical to the proven R10 core, offset by wm*32 / wn*32).
// Double-buffered smem, ONE barrier per BK=32 chunk.
// Smem rows padded to 40 halves: ldmatrix banks (i*20)%32 distinct -> conflict-free.
// ---------------------------------------------------------------------------
template <int NCH>
__device__ __forceinline__ void gemm64(const float* __restrict__ Ag, int lda,
                                       const __half* __restrict__ Bh, int ldb,
                                       int k0base, int m0,
                                       const float* __restrict__ bias,
                                       float* __restrict__ Cg) {
    __shared__ __align__(16) __half As[2][64 * 40];    // 2 x 5 KB
    __shared__ __align__(16) __half Bs[2][128 * 40];   // 2 x 10 KB

    const int tid  = threadIdx.x;
    const int lane = tid & 31;
    const int warp = tid >> 5;
    const int wm   = warp >> 2;        // 0..1
    const int wn   = warp & 3;         // 0..3
    const int g    = lane >> 2;
    const int t    = lane & 3;

    // A fill: thread -> row tid>>2 (0..63), halves (tid&3)*8
    const int ar_ = tid >> 2;
    const int ac8 = (tid & 3) * 8;

    // ldmatrix lane->row/koff (halves) — proven mapping
    const int a_row  = (lane & 7) + ((lane >> 3) & 1) * 8;
    const int a_koff = ((lane >> 4) & 1) * 8;
    const int b_row  = (lane & 7) + ((lane >> 4) & 1) * 8;
    const int b_koff = ((lane >> 3) & 1) * 8;

    float4 pa0, pa1;
    uint4  pb[2];

    auto loadAB = [&](int k0) {
        const float* p = Ag + (size_t)(m0 + ar_) * lda + k0 + ac8;
        pa0 = *(const float4*)p;
        pa1 = *(const float4*)(p + 4);
#pragma unroll
        for (int i = 0; i < 2; i++) {
            int e = tid + 256 * i;
            int r = e >> 2, c8 = (e & 3) * 8;
            pb[i] = *(const uint4*)(Bh + (size_t)r * ldb + k0 + c8);
        }
    };
    auto stsAB = [&](int buf) {
        *(uint4*)(As[buf] + ar_ * 40 + ac8) = f8_to_h8(pa0, pa1);
#pragma unroll
        for (int i = 0; i < 2; i++) {
            int e = tid + 256 * i;
            int r = e >> 2, c8 = (e & 3) * 8;
            *(uint4*)(Bs[buf] + r * 40 + c8) = pb[i];
        }
    };

    float acc[2][4][4];
#pragma unroll
    for (int mt = 0; mt < 2; mt++)
#pragma unroll
        for (int nt = 0; nt < 4; nt++)
#pragma unroll
            for (int q = 0; q < 4; q++) acc[mt][nt][q] = 0.f;

    auto compute = [&](int buf) {
#pragma unroll
        for (int ks = 0; ks < 2; ks++) {          // 2 k-steps of 16
            uint32_t a[2][4];
#pragma unroll
            for (int mt = 0; mt < 2; mt++) {
                uint32_t addr = smem_u32(As[buf] + (wm * 32 + mt * 16 + a_row) * 40
                                                  + ks * 16 + a_koff);
                LDMX4(a[mt][0], a[mt][1], a[mt][2], a[mt][3], addr);
            }
#pragma unroll
            for (int nt2 = 0; nt2 < 2; nt2++) {
                uint32_t b[4];
                uint32_t addr = smem_u32(Bs[buf] + (wn * 32 + nt2 * 16 + b_row) * 40
                                                  + ks * 16 + b_koff);
                LDMX4(b[0], b[1], b[2], b[3], addr);
#pragma unroll
                for (int sub = 0; sub < 2; sub++)
#pragma unroll
                    for (int mt = 0; mt < 2; mt++)
                        mma16816(acc[mt][nt2 * 2 + sub], a[mt],
                                 b[sub * 2], b[sub * 2 + 1]);
            }
        }
    };

    loadAB(k0base);
    stsAB(0);
    __syncthreads();
    for (int ch = 0; ch < NCH; ch++) {
        if (ch + 1 < NCH) loadAB(k0base + (ch + 1) * 32);   // gmem->regs, overlaps compute
        compute(ch & 1);
        if (ch + 1 < NCH) stsAB((ch + 1) & 1);              // idle buffer: no wait on peers
        __syncthreads();
    }

    // epilogue: c0:(g,2t) c1:(g,2t+1) c2:(g+8,2t) c3:(g+8,2t+1)
#pragma unroll
    for (int mt = 0; mt < 2; mt++) {
#pragma unroll
        for (int nt = 0; nt < 4; nt++) {
            int col = wn * 32 + nt * 8 + 2 * t;
            float bb0 = bias ? bias[col] : 0.f;
            float bb1 = bias ? bias[col + 1] : 0.f;
            int row = m0 + wm * 32 + mt * 16 + g;
            *(float2*)(Cg + (size_t)row * FOUT + col) =
                make_float2(acc[mt][nt][0] + bb0, acc[mt][nt][1] + bb1);
            *(float2*)(Cg + (size_t)(row + 8) * FOUT + col) =
                make_float2(acc[mt][nt][2] + bb0, acc[mt][nt][3] + bb1);
        }
    }
}

// ---------------------------------------------------------------------------
// K0a/K0b: weight transposes to half (unchanged, passing)
// ---------------------------------------------------------------------------
__global__ __launch_bounds__(256) void k_trWp(const float* __restrict__ Wp) {
    __shared__ float tb[32][33];
    const int k0 = blockIdx.x * 32, n0 = blockIdx.y * 32;
    const int tx = threadIdx.x & 31, ty0 = threadIdx.x >> 5;
#pragma unroll
    for (int dy = 0; dy < 32; dy += 8)
        tb[ty0 + dy][tx] = Wp[(size_t)(k0 + ty0 + dy) * FOUT + n0 + tx];
    __syncthreads();
#pragma unroll
    for (int dy = 0; dy < 32; dy += 8)
        g_WpTh[(size_t)(n0 + ty0 + dy) * FIN + k0 + tx] = __float2half_rn(tb[tx][ty0 + dy]);
}

__global__ __launch_bounds__(256) void k_trW1(const float* __restrict__ W1) {
    __shared__ float tb[32][33];
    const int z  = blockIdx.z;
    const int k0 = blockIdx.x * 32, f0 = blockIdx.y * 32;
    const int tx = threadIdx.x & 31, ty0 = threadIdx.x >> 5;
    const float* src = W1 + ((size_t)(z >> 1) * 2 * FOUT + (z & 1) * FOUT) * FOUT;
#pragma unroll
    for (int dy = 0; dy < 32; dy += 8)
        tb[ty0 + dy][tx] = src[(size_t)(k0 + ty0 + dy) * FOUT + f0 + tx];
    __syncthreads();
#pragma unroll
    for (int dy = 0; dy < 32; dy += 8)
        g_W1Th[z][(size_t)(f0 + ty0 + dy) * FOUT + k0 + tx] = __float2half_rn(tb[tx][ty0 + dy]);
}

// ---------------------------------------------------------------------------
// K1: split-K partials of emb = x @ Wp    (new 64-row double-buffered core)
// ---------------------------------------------------------------------------
__global__ __launch_bounds__(256) void k_emb(const float* __restrict__ x) {
    gemm64<KCHUNK / 32>(x, FIN, g_WpTh, FIN, blockIdx.y * KCHUNK,
                        blockIdx.x * 64, nullptr, g_part[blockIdx.y]);
}

// K1b: g_emb = sum of 4 partials + bp
__global__ __launch_bounds__(256) void k_reduce4(const float* __restrict__ bp) {
    const int i = (blockIdx.x * 256 + threadIdx.x) * 4;
    float4 s = *(const float4*)(g_part[0] + i);
#pragma unroll
    for (int p = 1; p < KSPLIT; p++) {
        float4 v = *(const float4*)(g_part[p] + i);
        s.x += v.x; s.y += v.y; s.z += v.z; s.w += v.w;
    }
    float4 bv = *(const float4*)(bp + (i & 127));
    s.x += bv.x; s.y += bv.y; s.z += bv.z; s.w += bv.w;
    *(float4*)(g_emb + i) = s;
}

// ---------------------------------------------------------------------------
// K2: g_AC[z] = emb @ W1Th[z]^T  (+b1 on even z)
// ---------------------------------------------------------------------------
__global__ __launch_bounds__(256) void k_proj(const float* __restrict__ b1) {
    const int z = blockIdx.y;
    const float* bias = ((z & 1) == 0) ? (b1 + (size_t)(z >> 1) * FOUT) : nullptr;
    gemm64<FOUT / 32>(g_emb, FOUT, g_W1Th[z], FOUT, 0, blockIdx.x * 64, bias, g_AC[z]);
}

// ---------------------------------------------------------------------------
// K3: pair scoring (unchanged from R10, passing): f-split 8 lanes/pair.
// S(i,k) = sum_f leaky(A[i][f]+C[k][f])*W2[h][f] + b2[h]
// out[b,h,j,i] = S(i, j+(j>=i)) for j<9;  out[b,h,9,:] = 0
// ---------------------------------------------------------------------------
__global__ __launch_bounds__(128) void k_pair4(const float* __restrict__ W2,
                                               const float* __restrict__ b2,
                                               float* __restrict__ out) {
    __shared__ __align__(16) float As[NNODES * 132];
    __shared__ __align__(16) float Cs[NNODES * 132];
    const int b = blockIdx.x, h = blockIdx.y;
    const int tid = threadIdx.x, lane = tid & 31, warp = tid >> 5;

    const float* Ap = g_AC[2 * h]     + (size_t)b * NNODES * FOUT;
    const float* Cp = g_AC[2 * h + 1] + (size_t)b * NNODES * FOUT;
    for (int e = tid; e < NNODES * 32; e += 128) {
        int r = e >> 5, c4 = e & 31;
        *(float4*)(As + r * 132 + c4 * 4) = *(const float4*)(Ap + r * FOUT + c4 * 4);
        *(float4*)(Cs + r * 132 + c4 * 4) = *(const float4*)(Cp + r * FOUT + c4 * 4);
    }
    const int sub = lane >> 3;
    const int fl  = lane & 7;
    float4 w2v[4];
#pragma unroll
    for (int j = 0; j < 4; j++) w2v[j] = *(const float4*)(W2 + h * FOUT + fl * 16 + j * 4);
    const float b2v = b2[h];
    __syncthreads();

    float* outp = out + ((size_t)b * NHEADS + h) * 100;
    for (int q = warp; q < 23; q += 4) {
        const int p = q * 4 + sub;
        float s = 0.f;
        int i = 0, kk = 0;
        if (p < 90) {
            i  = p / 9;
            kk = p - i * 9;
            const int k = kk + (kk >= i);
            const float* ar = As + i * 132 + fl * 16;
            const float* cr = Cs + k * 132 + fl * 16;
#pragma unroll
            for (int j = 0; j < 4; j++) {
                float4 av = *(const float4*)(ar + j * 4);
                float4 cv = *(const float4*)(cr + j * 4);
                float v0 = av.x + cv.x, v1 = av.y + cv.y;
                float v2 = av.z + cv.z, v3 = av.w + cv.w;
                v0 = (v0 > 0.f) ? v0 : 0.2f * v0;
                v1 = (v1 > 0.f) ? v1 : 0.2f * v1;
                v2 = (v2 > 0.f) ? v2 : 0.2f * v2;
                v3 = (v3 > 0.f) ? v3 : 0.2f * v3;
                s += v0 * w2v[j].x + v1 * w2v[j].y + v2 * w2v[j].z + v3 * w2v[j].w;
            }
        }
        s += __shfl_xor_sync(0xffffffffu, s, 4);
        s += __shfl_xor_sync(0xffffffffu, s, 2);
        s += __shfl_xor_sync(0xffffffffu, s, 1);
        if (p < 90 && fl == 0) outp[kk * 10 + i] = s + b2v;
    }
    if (tid < 10) outp[90 + tid] = 0.f;
}

// ---------------------------------------------------------------------------
// Launch. inputs: 0 object_features, 1 scene_geometry(unused), 2 Wp, 3 bp,
//                 4 W1, 5 b1, 6 W2, 7 b2, 8 d_max
// ---------------------------------------------------------------------------
extern "C" void kernel_launch(void* const* d_in, const int* in_sizes, int n_in,
                              void* d_out, int out_size) {
    const float* x  = (const float*)d_in[0];
    const float* Wp = (const float*)d_in[2];
    const float* bp = (const float*)d_in[3];
    const float* W1 = (const float*)d_in[4];
    const float* b1 = (const float*)d_in[5];
    const float* W2 = (const float*)d_in[6];
    const float* b2 = (const float*)d_in[7];
    float* out = (float*)d_out;

    dim3 gtw(FIN / 32, FOUT / 32);
    k_trWp<<<gtw, 256>>>(Wp);
    dim3 gt1(FOUT / 32, FOUT / 32, 16);
    k_trW1<<<gt1, 256>>>(W1);

    dim3 g1(MTOT / 64, KSPLIT);
    k_emb<<<g1, 256>>>(x);

    k_reduce4<<<MTOT * FOUT / (256 * 4), 256>>>(bp);

    dim3 g2(MTOT / 64, 16);
    k_proj<<<g2, 256>>>(b1);

    dim3 g3(NB, NHEADS);
    k_pair4<<<g3, 128>>>(W2, b2, out);
}

// round 13
// speedup vs baseline: 1.1406x; 1.0284x over previous
#include <cuda_runtime.h>
#include <cuda_fp16.h>
#include <cstdint>

#define NB      1024
#define NNODES  10
#define FIN     2048
#define FOUT    128
#define NHEADS  8
#define MTOT    (NB * NNODES)     // 10240
#define KSPLIT  8
#define KCHUNK  (FIN / KSPLIT)    // 256

// Scratch (allocation-guard-safe __device__ globals)
__device__ float  g_part[KSPLIT][MTOT * FOUT];   // 42 MB split-K partials
__device__ float  g_emb[MTOT * FOUT];            // 5.2 MB
__device__ float  g_AC[16][MTOT * FOUT];         // 84 MB: [z][m][f], z = 2h+half
__device__ __half g_WpTh[FOUT * FIN];            // Wp^T  [n=128][k=2048], half
__device__ __half g_W1Th[16][FOUT * FOUT];       // W1^T  [z][f=128][k=128], half

// ---------------------------------------------------------------------------
// helpers
// ---------------------------------------------------------------------------
__device__ __forceinline__ uint32_t smem_u32(const void* p) {
    return (uint32_t)__cvta_generic_to_shared(p);
}
__device__ __forceinline__ uint4 f8_to_h8(float4 a, float4 b) {
    __half2 h0 = __float22half2_rn(make_float2(a.x, a.y));
    __half2 h1 = __float22half2_rn(make_float2(a.z, a.w));
    __half2 h2 = __float22half2_rn(make_float2(b.x, b.y));
    __half2 h3 = __float22half2_rn(make_float2(b.z, b.w));
    uint4 r;
    r.x = *(uint32_t*)&h0; r.y = *(uint32_t*)&h1;
    r.z = *(uint32_t*)&h2; r.w = *(uint32_t*)&h3;
    return r;
}
__device__ __forceinline__ void mma16816(float* c, const uint32_t* a,
                                         uint32_t b0, uint32_t b1) {
    asm volatile(
        "mma.sync.aligned.m16n8k16.row.col.f32.f16.f16.f32 "
        "{%0,%1,%2,%3}, {%4,%5,%6,%7}, {%8,%9}, {%0,%1,%2,%3};"
        : "+f"(c[0]), "+f"(c[1]), "+f"(c[2]), "+f"(c[3])
        : "r"(a[0]), "r"(a[1]), "r"(a[2]), "r"(a[3]), "r"(b0), "r"(b1));
}
#define LDMX4(r0, r1, r2, r3, addr) \
    asm volatile("ldmatrix.sync.aligned.m8n8.x4.shared.b16 {%0,%1,%2,%3}, [%4];" \
        : "=r"(r0), "=r"(r1), "=r"(r2), "=r"(r3) : "r"(addr))

// ---------------------------------------------------------------------------
// FP16 MMA GEMM core v3: C[m0:m0+128][0:128] (+bias) = A(f32)[m0:][k-span] @ Bh^T
// 256 threads, 8 warps (2 m-groups x 4 n-groups), warptile 64x32.
// Fragment/ldmatrix maps identical to proven v2 (offset wm*64; mt 0..3).
// Double-buffered smem, ONE barrier per BK=32 chunk; 32 MMAs/warp/chunk.
// Rows padded to 40 halves: ldmatrix banks (i*20)%32 distinct -> conflict-free.
// ---------------------------------------------------------------------------
template <int NCH>
__device__ __forceinline__ void gemm128(const float* __restrict__ Ag, int lda,
                                        const __half* __restrict__ Bh, int ldb,
                                        int k0base, int m0,
                                        const float* __restrict__ bias,
                                        float* __restrict__ Cg) {
    __shared__ __align__(16) __half As[2][128 * 40];   // 2 x 10 KB
    __shared__ __align__(16) __half Bs[2][128 * 40];   // 2 x 10 KB

    const int tid  = threadIdx.x;
    const int lane = tid & 31;
    const int warp = tid >> 5;
    const int wm   = warp >> 2;        // 0..1  (rows wm*64 .. wm*64+63)
    const int wn   = warp & 3;         // 0..3  (cols wn*32 .. wn*32+31)
    const int g    = lane >> 2;
    const int t    = lane & 3;

    // ldmatrix lane->row/koff (halves) — proven mapping
    const int a_row  = (lane & 7) + ((lane >> 3) & 1) * 8;
    const int a_koff = ((lane >> 4) & 1) * 8;
    const int b_row  = (lane & 7) + ((lane >> 4) & 1) * 8;
    const int b_koff = ((lane >> 3) & 1) * 8;

    float4 paA[2], paB[2];
    uint4  pb[2];

    // fill mapping (proven): element e covers row e>>2, halves (e&3)*8
    auto loadAB = [&](int k0) {
#pragma unroll
        for (int i = 0; i < 2; i++) {
            int e = tid + 256 * i;
            int r = e >> 2, c8 = (e & 3) * 8;
            const float* p = Ag + (size_t)(m0 + r) * lda + k0 + c8;
            paA[i] = *(const float4*)p;
            paB[i] = *(const float4*)(p + 4);
            pb[i]  = *(const uint4*)(Bh + (size_t)r * ldb + k0 + c8);
        }
    };
    auto stsAB = [&](int buf) {
#pragma unroll
        for (int i = 0; i < 2; i++) {
            int e = tid + 256 * i;
            int r = e >> 2, c8 = (e & 3) * 8;
            *(uint4*)(As[buf] + r * 40 + c8) = f8_to_h8(paA[i], paB[i]);
            *(uint4*)(Bs[buf] + r * 40 + c8) = pb[i];
        }
    };

    float acc[4][4][4];
#pragma unroll
    for (int mt = 0; mt < 4; mt++)
#pragma unroll
        for (int nt = 0; nt < 4; nt++)
#pragma unroll
            for (int q = 0; q < 4; q++) acc[mt][nt][q] = 0.f;

    auto compute = [&](int buf) {
#pragma unroll
        for (int ks = 0; ks < 2; ks++) {          // 2 k-steps of 16
            uint32_t a[4][4];
#pragma unroll
            for (int mt = 0; mt < 4; mt++) {
                uint32_t addr = smem_u32(As[buf] + (wm * 64 + mt * 16 + a_row) * 40
                                                  + ks * 16 + a_koff);
                LDMX4(a[mt][0], a[mt][1], a[mt][2], a[mt][3], addr);
            }
#pragma unroll
            for (int nt2 = 0; nt2 < 2; nt2++) {
                uint32_t b[4];
                uint32_t addr = smem_u32(Bs[buf] + (wn * 32 + nt2 * 16 + b_row) * 40
                                                  + ks * 16 + b_koff);
                LDMX4(b[0], b[1], b[2], b[3], addr);
#pragma unroll
                for (int sub = 0; sub < 2; sub++)
#pragma unroll
                    for (int mt = 0; mt < 4; mt++)
                        mma16816(acc[mt][nt2 * 2 + sub], a[mt],
                                 b[sub * 2], b[sub * 2 + 1]);
            }
        }
    };

    loadAB(k0base);
    stsAB(0);
    __syncthreads();
    for (int ch = 0; ch < NCH; ch++) {
        if (ch + 1 < NCH) loadAB(k0base + (ch + 1) * 32);   // gmem->regs overlap
        compute(ch & 1);
        if (ch + 1 < NCH) stsAB((ch + 1) & 1);              // idle buffer
        __syncthreads();
    }

    // epilogue: c0:(g,2t) c1:(g,2t+1) c2:(g+8,2t) c3:(g+8,2t+1)
#pragma unroll
    for (int mt = 0; mt < 4; mt++) {
#pragma unroll
        for (int nt = 0; nt < 4; nt++) {
            int col = wn * 32 + nt * 8 + 2 * t;
            float bb0 = bias ? bias[col] : 0.f;
            float bb1 = bias ? bias[col + 1] : 0.f;
            int row = m0 + wm * 64 + mt * 16 + g;
            *(float2*)(Cg + (size_t)row * FOUT + col) =
                make_float2(acc[mt][nt][0] + bb0, acc[mt][nt][1] + bb1);
            *(float2*)(Cg + (size_t)(row + 8) * FOUT + col) =
                make_float2(acc[mt][nt][2] + bb0, acc[mt][nt][3] + bb1);
        }
    }
}

// ---------------------------------------------------------------------------
// K0a/K0b: weight transposes to half (unchanged, passing)
// ---------------------------------------------------------------------------
__global__ __launch_bounds__(256) void k_trWp(const float* __restrict__ Wp) {
    __shared__ float tb[32][33];
    const int k0 = blockIdx.x * 32, n0 = blockIdx.y * 32;
    const int tx = threadIdx.x & 31, ty0 = threadIdx.x >> 5;
#pragma unroll
    for (int dy = 0; dy < 32; dy += 8)
        tb[ty0 + dy][tx] = Wp[(size_t)(k0 + ty0 + dy) * FOUT + n0 + tx];
    __syncthreads();
#pragma unroll
    for (int dy = 0; dy < 32; dy += 8)
        g_WpTh[(size_t)(n0 + ty0 + dy) * FIN + k0 + tx] = __float2half_rn(tb[tx][ty0 + dy]);
}

__global__ __launch_bounds__(256) void k_trW1(const float* __restrict__ W1) {
    __shared__ float tb[32][33];
    const int z  = blockIdx.z;
    const int k0 = blockIdx.x * 32, f0 = blockIdx.y * 32;
    const int tx = threadIdx.x & 31, ty0 = threadIdx.x >> 5;
    const float* src = W1 + ((size_t)(z >> 1) * 2 * FOUT + (z & 1) * FOUT) * FOUT;
#pragma unroll
    for (int dy = 0; dy < 32; dy += 8)
        tb[ty0 + dy][tx] = src[(size_t)(k0 + ty0 + dy) * FOUT + f0 + tx];
    __syncthreads();
#pragma unroll
    for (int dy = 0; dy < 32; dy += 8)
        g_W1Th[z][(size_t)(f0 + ty0 + dy) * FOUT + k0 + tx] = __float2half_rn(tb[tx][ty0 + dy]);
}

// ---------------------------------------------------------------------------
// K1: split-K partials of emb = x @ Wp    (128-row double-buffered core)
// ---------------------------------------------------------------------------
__global__ __launch_bounds__(256) void k_emb(const float* __restrict__ x) {
    gemm128<KCHUNK / 32>(x, FIN, g_WpTh, FIN, blockIdx.y * KCHUNK,
                         blockIdx.x * 128, nullptr, g_part[blockIdx.y]);
}

// K1b: g_emb = sum of 8 partials + bp
__global__ __launch_bounds__(256) void k_reduce8(const float* __restrict__ bp) {
    const int i = (blockIdx.x * 256 + threadIdx.x) * 4;
    float4 s = *(const float4*)(g_part[0] + i);
#pragma unroll
    for (int p = 1; p < KSPLIT; p++) {
        float4 v = *(const float4*)(g_part[p] + i);
        s.x += v.x; s.y += v.y; s.z += v.z; s.w += v.w;
    }
    float4 bv = *(const float4*)(bp + (i & 127));
    s.x += bv.x; s.y += bv.y; s.z += bv.z; s.w += bv.w;
    *(float4*)(g_emb + i) = s;
}

// ---------------------------------------------------------------------------
// K2: g_AC[z] = emb @ W1Th[z]^T  (+b1 on even z)
// ---------------------------------------------------------------------------
__global__ __launch_bounds__(256) void k_proj(const float* __restrict__ b1) {
    const int z = blockIdx.y;
    const float* bias = ((z & 1) == 0) ? (b1 + (size_t)(z >> 1) * FOUT) : nullptr;
    gemm128<FOUT / 32>(g_emb, FOUT, g_W1Th[z], FOUT, 0, blockIdx.x * 128, bias, g_AC[z]);
}

// ---------------------------------------------------------------------------
// K3: pair scoring (unchanged from R10, passing): f-split 8 lanes/pair.
// S(i,k) = sum_f leaky(A[i][f]+C[k][f])*W2[h][f] + b2[h]
// out[b,h,j,i] = S(i, j+(j>=i)) for j<9;  out[b,h,9,:] = 0
// ---------------------------------------------------------------------------
__global__ __launch_bounds__(128) void k_pair4(const float* __restrict__ W2,
                                               const float* __restrict__ b2,
                                               float* __restrict__ out) {
    __shared__ __align__(16) float As[NNODES * 132];
    __shared__ __align__(16) float Cs[NNODES * 132];
    const int b = blockIdx.x, h = blockIdx.y;
    const int tid = threadIdx.x, lane = tid & 31, warp = tid >> 5;

    const float* Ap = g_AC[2 * h]     + (size_t)b * NNODES * FOUT;
    const float* Cp = g_AC[2 * h + 1] + (size_t)b * NNODES * FOUT;
    for (int e = tid; e < NNODES * 32; e += 128) {
        int r = e >> 5, c4 = e & 31;
        *(float4*)(As + r * 132 + c4 * 4) = *(const float4*)(Ap + r * FOUT + c4 * 4);
        *(float4*)(Cs + r * 132 + c4 * 4) = *(const float4*)(Cp + r * FOUT + c4 * 4);
    }
    const int sub = lane >> 3;
    const int fl  = lane & 7;
    float4 w2v[4];
#pragma unroll
    for (int j = 0; j < 4; j++) w2v[j] = *(const float4*)(W2 + h * FOUT + fl * 16 + j * 4);
    const float b2v = b2[h];
    __syncthreads();

    float* outp = out + ((size_t)b * NHEADS + h) * 100;
    for (int q = warp; q < 23; q += 4) {
        const int p = q * 4 + sub;
        float s = 0.f;
        int i = 0, kk = 0;
        if (p < 90) {
            i  = p / 9;
            kk = p - i * 9;
            const int k = kk + (kk >= i);
            const float* ar = As + i * 132 + fl * 16;
            const float* cr = Cs + k * 132 + fl * 16;
#pragma unroll
            for (int j = 0; j < 4; j++) {
                float4 av = *(const float4*)(ar + j * 4);
                float4 cv = *(const float4*)(cr + j * 4);
                float v0 = av.x + cv.x, v1 = av.y + cv.y;
                float v2 = av.z + cv.z, v3 = av.w + cv.w;
                v0 = (v0 > 0.f) ? v0 : 0.2f * v0;
                v1 = (v1 > 0.f) ? v1 : 0.2f * v1;
                v2 = (v2 > 0.f) ? v2 : 0.2f * v2;
                v3 = (v3 > 0.f) ? v3 : 0.2f * v3;
                s += v0 * w2v[j].x + v1 * w2v[j].y + v2 * w2v[j].z + v3 * w2v[j].w;
            }
        }
        s += __shfl_xor_sync(0xffffffffu, s, 4);
        s += __shfl_xor_sync(0xffffffffu, s, 2);
        s += __shfl_xor_sync(0xffffffffu, s, 1);
        if (p < 90 && fl == 0) outp[kk * 10 + i] = s + b2v;
    }
    if (tid < 10) outp[90 + tid] = 0.f;
}

// ---------------------------------------------------------------------------
// Launch. inputs: 0 object_features, 1 scene_geometry(unused), 2 Wp, 3 bp,
//                 4 W1, 5 b1, 6 W2, 7 b2, 8 d_max
// ---------------------------------------------------------------------------
extern "C" void kernel_launch(void* const* d_in, const int* in_sizes, int n_in,
                              void* d_out, int out_size) {
    const float* x  = (const float*)d_in[0];
    const float* Wp = (const float*)d_in[2];
    const float* bp = (const float*)d_in[3];
    const float* W1 = (const float*)d_in[4];
    const float* b1 = (const float*)d_in[5];
    const float* W2 = (const float*)d_in[6];
    const float* b2 = (const float*)d_in[7];
    float* out = (float*)d_out;

    dim3 gtw(FIN / 32, FOUT / 32);
    k_trWp<<<gtw, 256>>>(Wp);
    dim3 gt1(FOUT / 32, FOUT / 32, 16);
    k_trW1<<<gt1, 256>>>(W1);

    dim3 g1(MTOT / 128, KSPLIT);
    k_emb<<<g1, 256>>>(x);

    k_reduce8<<<MTOT * FOUT / (256 * 4), 256>>>(bp);

    dim3 g2(MTOT / 128, 16);
    k_proj<<<g2, 256>>>(b1);

    dim3 g3(NB, NHEADS);
    k_pair4<<<g3, 128>>>(W2, b2, out);
}

// round 14
// speedup vs baseline: 1.6286x; 1.4278x over previous
#include <cuda_runtime.h>
#include <cuda_fp16.h>
#include <cstdint>

#define NB      1024
#define NNODES  10
#define FIN     2048
#define FOUT    128
#define NHEADS  8
#define MTOT    (NB * NNODES)     // 10240
#define KSPLIT  8
#define KCHUNK  (FIN / KSPLIT)    // 256

// Scratch (allocation-guard-safe __device__ globals) — ALL half now
__device__ __half g_parth[KSPLIT][MTOT * FOUT];  // 21 MB split-K partials
__device__ __half g_embh[MTOT * FOUT];           // 2.6 MB
__device__ __half g_ACh[16][MTOT * FOUT];        // 42 MB: [z][m][f], z = 2h+half
__device__ __half g_WpTh[FOUT * FIN];            // Wp^T  [n=128][k=2048]
__device__ __half g_W1Th[16][FOUT * FOUT];       // W1^T  [z][f=128][k=128]

// ---------------------------------------------------------------------------
// helpers
// ---------------------------------------------------------------------------
__device__ __forceinline__ uint32_t smem_u32(const void* p) {
    return (uint32_t)__cvta_generic_to_shared(p);
}
__device__ __forceinline__ uint4 f8_to_h8(float4 a, float4 b) {
    __half2 h0 = __float22half2_rn(make_float2(a.x, a.y));
    __half2 h1 = __float22half2_rn(make_float2(a.z, a.w));
    __half2 h2 = __float22half2_rn(make_float2(b.x, b.y));
    __half2 h3 = __float22half2_rn(make_float2(b.z, b.w));
    uint4 r;
    r.x = *(uint32_t*)&h0; r.y = *(uint32_t*)&h1;
    r.z = *(uint32_t*)&h2; r.w = *(uint32_t*)&h3;
    return r;
}
__device__ __forceinline__ void mma16816(float* c, const uint32_t* a,
                                         uint32_t b0, uint32_t b1) {
    asm volatile(
        "mma.sync.aligned.m16n8k16.row.col.f32.f16.f16.f32 "
        "{%0,%1,%2,%3}, {%4,%5,%6,%7}, {%8,%9}, {%0,%1,%2,%3};"
        : "+f"(c[0]), "+f"(c[1]), "+f"(c[2]), "+f"(c[3])
        : "r"(a[0]), "r"(a[1]), "r"(a[2]), "r"(a[3]), "r"(b0), "r"(b1));
}
#define LDMX4(r0, r1, r2, r3, addr) \
    asm volatile("ldmatrix.sync.aligned.m8n8.x4.shared.b16 {%0,%1,%2,%3}, [%4];" \
        : "=r"(r0), "=r"(r1), "=r"(r2), "=r"(r3) : "r"(addr))

// ---------------------------------------------------------------------------
// FP16 MMA GEMM core v4: C[m0:m0+128][0:128](half,+bias) = A @ Bh^T
// A is f32 (AH=false, converted inline) or half (AH=true, direct uint4 path).
// 256 threads, 8 warps (2m x 4n), warptile 64x32, double-buffered, 1 barrier
// per BK=32 chunk. Rows padded to 40 halves -> ldmatrix conflict-free.
// ---------------------------------------------------------------------------
template <int NCH, bool AH>
__device__ __forceinline__ void gemm128h(const void* __restrict__ Ag_, int lda,
                                         const __half* __restrict__ Bh, int ldb,
                                         int k0base, int m0,
                                         const float* __restrict__ bias,
                                         __half* __restrict__ Cg) {
    __shared__ __align__(16) __half As[2][128 * 40];   // 2 x 10 KB
    __shared__ __align__(16) __half Bs[2][128 * 40];   // 2 x 10 KB

    const int tid  = threadIdx.x;
    const int lane = tid & 31;
    const int warp = tid >> 5;
    const int wm   = warp >> 2;
    const int wn   = warp & 3;
    const int g    = lane >> 2;
    const int t    = lane & 3;

    const int a_row  = (lane & 7) + ((lane >> 3) & 1) * 8;
    const int a_koff = ((lane >> 4) & 1) * 8;
    const int b_row  = (lane & 7) + ((lane >> 4) & 1) * 8;
    const int b_koff = ((lane >> 3) & 1) * 8;

    float4 paA[2], paB[2];    // used when !AH
    uint4  pah[2];            // used when AH
    uint4  pb[2];

    auto loadAB = [&](int k0) {
#pragma unroll
        for (int i = 0; i < 2; i++) {
            int e = tid + 256 * i;
            int r = e >> 2, c8 = (e & 3) * 8;
            if (AH) {
                const __half* Ah = (const __half*)Ag_;
                pah[i] = *(const uint4*)(Ah + (size_t)(m0 + r) * lda + k0 + c8);
            } else {
                const float* Af = (const float*)Ag_;
                const float* p = Af + (size_t)(m0 + r) * lda + k0 + c8;
                paA[i] = *(const float4*)p;
                paB[i] = *(const float4*)(p + 4);
            }
            pb[i] = *(const uint4*)(Bh + (size_t)r * ldb + k0 + c8);
        }
    };
    auto stsAB = [&](int buf) {
#pragma unroll
        for (int i = 0; i < 2; i++) {
            int e = tid + 256 * i;
            int r = e >> 2, c8 = (e & 3) * 8;
            *(uint4*)(As[buf] + r * 40 + c8) = AH ? pah[i] : f8_to_h8(paA[i], paB[i]);
            *(uint4*)(Bs[buf] + r * 40 + c8) = pb[i];
        }
    };

    float acc[4][4][4];
#pragma unroll
    for (int mt = 0; mt < 4; mt++)
#pragma unroll
        for (int nt = 0; nt < 4; nt++)
#pragma unroll
            for (int q = 0; q < 4; q++) acc[mt][nt][q] = 0.f;

    auto compute = [&](int buf) {
#pragma unroll
        for (int ks = 0; ks < 2; ks++) {
            uint32_t a[4][4];
#pragma unroll
            for (int mt = 0; mt < 4; mt++) {
                uint32_t addr = smem_u32(As[buf] + (wm * 64 + mt * 16 + a_row) * 40
                                                  + ks * 16 + a_koff);
                LDMX4(a[mt][0], a[mt][1], a[mt][2], a[mt][3], addr);
            }
#pragma unroll
            for (int nt2 = 0; nt2 < 2; nt2++) {
                uint32_t b[4];
                uint32_t addr = smem_u32(Bs[buf] + (wn * 32 + nt2 * 16 + b_row) * 40
                                                  + ks * 16 + b_koff);
                LDMX4(b[0], b[1], b[2], b[3], addr);
#pragma unroll
                for (int sub = 0; sub < 2; sub++)
#pragma unroll
                    for (int mt = 0; mt < 4; mt++)
                        mma16816(acc[mt][nt2 * 2 + sub], a[mt],
                                 b[sub * 2], b[sub * 2 + 1]);
            }
        }
    };

    loadAB(k0base);
    stsAB(0);
    __syncthreads();
    for (int ch = 0; ch < NCH; ch++) {
        if (ch + 1 < NCH) loadAB(k0base + (ch + 1) * 32);
        compute(ch & 1);
        if (ch + 1 < NCH) stsAB((ch + 1) & 1);
        __syncthreads();
    }

    // epilogue: half2 stores. c0:(g,2t) c1:(g,2t+1) c2:(g+8,2t) c3:(g+8,2t+1)
#pragma unroll
    for (int mt = 0; mt < 4; mt++) {
#pragma unroll
        for (int nt = 0; nt < 4; nt++) {
            int col = wn * 32 + nt * 8 + 2 * t;
            float bb0 = bias ? bias[col] : 0.f;
            float bb1 = bias ? bias[col + 1] : 0.f;
            int row = m0 + wm * 64 + mt * 16 + g;
            *(__half2*)(Cg + (size_t)row * FOUT + col) =
                __floats2half2_rn(acc[mt][nt][0] + bb0, acc[mt][nt][1] + bb1);
            *(__half2*)(Cg + (size_t)(row + 8) * FOUT + col) =
                __floats2half2_rn(acc[mt][nt][2] + bb0, acc[mt][nt][3] + bb1);
        }
    }
}

// ---------------------------------------------------------------------------
// K0a/K0b: weight transposes to half (unchanged, passing)
// ---------------------------------------------------------------------------
__global__ __launch_bounds__(256) void k_trWp(const float* __restrict__ Wp) {
    __shared__ float tb[32][33];
    const int k0 = blockIdx.x * 32, n0 = blockIdx.y * 32;
    const int tx = threadIdx.x & 31, ty0 = threadIdx.x >> 5;
#pragma unroll
    for (int dy = 0; dy < 32; dy += 8)
        tb[ty0 + dy][tx] = Wp[(size_t)(k0 + ty0 + dy) * FOUT + n0 + tx];
    __syncthreads();
#pragma unroll
    for (int dy = 0; dy < 32; dy += 8)
        g_WpTh[(size_t)(n0 + ty0 + dy) * FIN + k0 + tx] = __float2half_rn(tb[tx][ty0 + dy]);
}

__global__ __launch_bounds__(256) void k_trW1(const float* __restrict__ W1) {
    __shared__ float tb[32][33];
    const int z  = blockIdx.z;
    const int k0 = blockIdx.x * 32, f0 = blockIdx.y * 32;
    const int tx = threadIdx.x & 31, ty0 = threadIdx.x >> 5;
    const float* src = W1 + ((size_t)(z >> 1) * 2 * FOUT + (z & 1) * FOUT) * FOUT;
#pragma unroll
    for (int dy = 0; dy < 32; dy += 8)
        tb[ty0 + dy][tx] = src[(size_t)(k0 + ty0 + dy) * FOUT + f0 + tx];
    __syncthreads();
#pragma unroll
    for (int dy = 0; dy < 32; dy += 8)
        g_W1Th[z][(size_t)(f0 + ty0 + dy) * FOUT + k0 + tx] = __float2half_rn(tb[tx][ty0 + dy]);
}

// ---------------------------------------------------------------------------
// K1: split-K partials (half) of emb = x @ Wp
// ---------------------------------------------------------------------------
__global__ __launch_bounds__(256) void k_emb(const float* __restrict__ x) {
    gemm128h<KCHUNK / 32, false>(x, FIN, g_WpTh, FIN, blockIdx.y * KCHUNK,
                                 blockIdx.x * 128, nullptr, g_parth[blockIdx.y]);
}

// K1b: g_embh = half(sum of 8 half partials + bp); sums in fp32.
__global__ __launch_bounds__(256) void k_reduce8(const float* __restrict__ bp) {
    const int i = (blockIdx.x * 256 + threadIdx.x) * 8;   // half index
    float a[8];
#pragma unroll
    for (int j = 0; j < 8; j++) a[j] = 0.f;
#pragma unroll
    for (int p = 0; p < KSPLIT; p++) {
        uint4 v = *(const uint4*)(g_parth[p] + i);
        __half2* h = (__half2*)&v;
#pragma unroll
        for (int j = 0; j < 4; j++) {
            float2 f = __half22float2(h[j]);
            a[2 * j] += f.x; a[2 * j + 1] += f.y;
        }
    }
    const int cb = i & 127;
    uint4 o;
    __half2* oh = (__half2*)&o;
#pragma unroll
    for (int j = 0; j < 4; j++)
        oh[j] = __floats2half2_rn(a[2 * j] + bp[cb + 2 * j],
                                  a[2 * j + 1] + bp[cb + 2 * j + 1]);
    *(uint4*)(g_embh + i) = o;
}

// ---------------------------------------------------------------------------
// K2: g_ACh[z] = emb @ W1Th[z]^T  (+b1 on even z)   — all-half operand path
// ---------------------------------------------------------------------------
__global__ __launch_bounds__(256) void k_proj(const float* __restrict__ b1) {
    const int z = blockIdx.y;
    const float* bias = ((z & 1) == 0) ? (b1 + (size_t)(z >> 1) * FOUT) : nullptr;
    gemm128h<FOUT / 32, true>(g_embh, FOUT, g_W1Th[z], FOUT, 0,
                              blockIdx.x * 128, bias, g_ACh[z]);
}

// ---------------------------------------------------------------------------
// K3: pair scoring from half A/C: f-split 8 lanes/pair, 4 pairs/warp-iter.
// S(i,k) = sum_f leaky(A[i][f]+C[k][f])*W2[h][f] + b2[h]
// out[b,h,j,i] = S(i, j+(j>=i)) for j<9;  out[b,h,9,:] = 0
// ---------------------------------------------------------------------------
__global__ __launch_bounds__(128) void k_pair4(const float* __restrict__ W2,
                                               const float* __restrict__ b2,
                                               float* __restrict__ out) {
    __shared__ __align__(16) __half As[NNODES * 136];
    __shared__ __align__(16) __half Cs[NNODES * 136];
    const int b = blockIdx.x, h = blockIdx.y;
    const int tid = threadIdx.x, lane = tid & 31, warp = tid >> 5;

    const __half* Ap = g_ACh[2 * h]     + (size_t)b * NNODES * FOUT;
    const __half* Cp = g_ACh[2 * h + 1] + (size_t)b * NNODES * FOUT;
    for (int e = tid; e < NNODES * 16; e += 128) {
        int r = e >> 4, c8 = (e & 15) * 8;
        *(uint4*)(As + r * 136 + c8) = *(const uint4*)(Ap + r * FOUT + c8);
        *(uint4*)(Cs + r * 136 + c8) = *(const uint4*)(Cp + r * FOUT + c8);
    }
    const int sub = lane >> 3;       // pair-in-group 0..3
    const int fl  = lane & 7;        // f-slice 0..7 (16 cols each)
    float4 w2v[4];
#pragma unroll
    for (int j = 0; j < 4; j++) w2v[j] = *(const float4*)(W2 + h * FOUT + fl * 16 + j * 4);
    const float b2v = b2[h];
    __syncthreads();

    float* outp = out + ((size_t)b * NHEADS + h) * 100;
    for (int q = warp; q < 23; q += 4) {
        const int p = q * 4 + sub;
        float s = 0.f;
        int i = 0, kk = 0;
        if (p < 90) {
            i  = p / 9;
            kk = p - i * 9;
            const int k = kk + (kk >= i);
            const __half* ar = As + i * 136 + fl * 16;
            const __half* cr = Cs + k * 136 + fl * 16;
            uint4 ua0 = *(const uint4*)ar;
            uint4 ua1 = *(const uint4*)(ar + 8);
            uint4 uc0 = *(const uint4*)cr;
            uint4 uc1 = *(const uint4*)(cr + 8);
            float v[16];
            __half2* ha0 = (__half2*)&ua0; __half2* hc0 = (__half2*)&uc0;
            __half2* ha1 = (__half2*)&ua1; __half2* hc1 = (__half2*)&uc1;
#pragma unroll
            for (int jj = 0; jj < 4; jj++) {
                float2 fa = __half22float2(ha0[jj]);
                float2 fc = __half22float2(hc0[jj]);
                v[2 * jj]     = fa.x + fc.x;
                v[2 * jj + 1] = fa.y + fc.y;
                float2 fa1 = __half22float2(ha1[jj]);
                float2 fc1 = __half22float2(hc1[jj]);
                v[8 + 2 * jj]     = fa1.x + fc1.x;
                v[8 + 2 * jj + 1] = fa1.y + fc1.y;
            }
#pragma unroll
            for (int j = 0; j < 4; j++) {
                float v0 = v[4 * j], v1 = v[4 * j + 1], v2 = v[4 * j + 2], v3 = v[4 * j + 3];
                v0 = (v0 > 0.f) ? v0 : 0.2f * v0;
                v1 = (v1 > 0.f) ? v1 : 0.2f * v1;
                v2 = (v2 > 0.f) ? v2 : 0.2f * v2;
                v3 = (v3 > 0.f) ? v3 : 0.2f * v3;
                s += v0 * w2v[j].x + v1 * w2v[j].y + v2 * w2v[j].z + v3 * w2v[j].w;
            }
        }
        s += __shfl_xor_sync(0xffffffffu, s, 4);
        s += __shfl_xor_sync(0xffffffffu, s, 2);
        s += __shfl_xor_sync(0xffffffffu, s, 1);
        if (p < 90 && fl == 0) outp[kk * 10 + i] = s + b2v;
    }
    if (tid < 10) outp[90 + tid] = 0.f;
}

// ---------------------------------------------------------------------------
// Launch. inputs: 0 object_features, 1 scene_geometry(unused), 2 Wp, 3 bp,
//                 4 W1, 5 b1, 6 W2, 7 b2, 8 d_max
// ---------------------------------------------------------------------------
extern "C" void kernel_launch(void* const* d_in, const int* in_sizes, int n_in,
                              void* d_out, int out_size) {
    const float* x  = (const float*)d_in[0];
    const float* Wp = (const float*)d_in[2];
    const float* bp = (const float*)d_in[3];
    const float* W1 = (const float*)d_in[4];
    const float* b1 = (const float*)d_in[5];
    const float* W2 = (const float*)d_in[6];
    const float* b2 = (const float*)d_in[7];
    float* out = (float*)d_out;

    dim3 gtw(FIN / 32, FOUT / 32);
    k_trWp<<<gtw, 256>>>(Wp);
    dim3 gt1(FOUT / 32, FOUT / 32, 16);
    k_trW1<<<gt1, 256>>>(W1);

    dim3 g1(MTOT / 128, KSPLIT);
    k_emb<<<g1, 256>>>(x);

    k_reduce8<<<MTOT * FOUT / (256 * 8), 256>>>(bp);

    dim3 g2(MTOT / 128, 16);
    k_proj<<<g2, 256>>>(b1);

    dim3 g3(NB, NHEADS);
    k_pair4<<<g3, 128>>>(W2, b2, out);
}

// round 15
// speedup vs baseline: 1.6490x; 1.0126x over previous
#include <cuda_runtime.h>
#include <cuda_fp16.h>
#include <cstdint>

#define NB      1024
#define NNODES  10
#define FIN     2048
#define FOUT    128
#define NHEADS  8
#define MTOT    (NB * NNODES)     // 10240
#define KSPLIT  8
#define KCHUNK  (FIN / KSPLIT)    // 256

// Scratch (allocation-guard-safe __device__ globals) — ALL half now
__device__ __half g_parth[KSPLIT][MTOT * FOUT];  // 21 MB split-K partials
__device__ __half g_embh[MTOT * FOUT];           // 2.6 MB
__device__ __half g_ACh[16][MTOT * FOUT];        // 42 MB: [z][m][f], z = 2h+half
__device__ __half g_WpTh[FOUT * FIN];            // Wp^T  [n=128][k=2048]
__device__ __half g_W1Th[16][FOUT * FOUT];       // W1^T  [z][f=128][k=128]

// ---------------------------------------------------------------------------
// helpers
// ---------------------------------------------------------------------------
__device__ __forceinline__ uint32_t smem_u32(const void* p) {
    return (uint32_t)__cvta_generic_to_shared(p);
}
__device__ __forceinline__ uint4 f8_to_h8(float4 a, float4 b) {
    __half2 h0 = __float22half2_rn(make_float2(a.x, a.y));
    __half2 h1 = __float22half2_rn(make_float2(a.z, a.w));
    __half2 h2 = __float22half2_rn(make_float2(b.x, b.y));
    __half2 h3 = __float22half2_rn(make_float2(b.z, b.w));
    uint4 r;
    r.x = *(uint32_t*)&h0; r.y = *(uint32_t*)&h1;
    r.z = *(uint32_t*)&h2; r.w = *(uint32_t*)&h3;
    return r;
}
__device__ __forceinline__ void mma16816(float* c, const uint32_t* a,
                                         uint32_t b0, uint32_t b1) {
    asm volatile(
        "mma.sync.aligned.m16n8k16.row.col.f32.f16.f16.f32 "
        "{%0,%1,%2,%3}, {%4,%5,%6,%7}, {%8,%9}, {%0,%1,%2,%3};"
        : "+f"(c[0]), "+f"(c[1]), "+f"(c[2]), "+f"(c[3])
        : "r"(a[0]), "r"(a[1]), "r"(a[2]), "r"(a[3]), "r"(b0), "r"(b1));
}
#define LDMX4(r0, r1, r2, r3, addr) \
    asm volatile("ldmatrix.sync.aligned.m8n8.x4.shared.b16 {%0,%1,%2,%3}, [%4];" \
        : "=r"(r0), "=r"(r1), "=r"(r2), "=r"(r3) : "r"(addr))

// ---------------------------------------------------------------------------
// FP16 MMA GEMM core v4: C[m0:m0+128][0:128](half,+bias) = A @ Bh^T
// A is f32 (AH=false, converted inline) or half (AH=true, direct uint4 path).
// 256 threads, 8 warps (2m x 4n), warptile 64x32, double-buffered, 1 barrier
// per BK=32 chunk. Rows padded to 40 halves -> ldmatrix conflict-free.
// ---------------------------------------------------------------------------
template <int NCH, bool AH>
__device__ __forceinline__ void gemm128h(const void* __restrict__ Ag_, int lda,
                                         const __half* __restrict__ Bh, int ldb,
                                         int k0base, int m0,
                                         const float* __restrict__ bias,
                                         __half* __restrict__ Cg) {
    __shared__ __align__(16) __half As[2][128 * 40];   // 2 x 10 KB
    __shared__ __align__(16) __half Bs[2][128 * 40];   // 2 x 10 KB

    const int tid  = threadIdx.x;
    const int lane = tid & 31;
    const int warp = tid >> 5;
    const int wm   = warp >> 2;
    const int wn   = warp & 3;
    const int g    = lane >> 2;
    const int t    = lane & 3;

    const int a_row  = (lane & 7) + ((lane >> 3) & 1) * 8;
    const int a_koff = ((lane >> 4) & 1) * 8;
    const int b_row  = (lane & 7) + ((lane >> 4) & 1) * 8;
    const int b_koff = ((lane >> 3) & 1) * 8;

    float4 paA[2], paB[2];    // used when !AH
    uint4  pah[2];            // used when AH
    uint4  pb[2];

    auto loadAB = [&](int k0) {
#pragma unroll
        for (int i = 0; i < 2; i++) {
            int e = tid + 256 * i;
            int r = e >> 2, c8 = (e & 3) * 8;
            if (AH) {
                const __half* Ah = (const __half*)Ag_;
                pah[i] = *(const uint4*)(Ah + (size_t)(m0 + r) * lda + k0 + c8);
            } else {
                const float* Af = (const float*)Ag_;
                const float* p = Af + (size_t)(m0 + r) * lda + k0 + c8;
                paA[i] = *(const float4*)p;
                paB[i] = *(const float4*)(p + 4);
            }
            pb[i] = *(const uint4*)(Bh + (size_t)r * ldb + k0 + c8);
        }
    };
    auto stsAB = [&](int buf) {
#pragma unroll
        for (int i = 0; i < 2; i++) {
            int e = tid + 256 * i;
            int r = e >> 2, c8 = (e & 3) * 8;
            *(uint4*)(As[buf] + r * 40 + c8) = AH ? pah[i] : f8_to_h8(paA[i], paB[i]);
            *(uint4*)(Bs[buf] + r * 40 + c8) = pb[i];
        }
    };

    float acc[4][4][4];
#pragma unroll
    for (int mt = 0; mt < 4; mt++)
#pragma unroll
        for (int nt = 0; nt < 4; nt++)
#pragma unroll
            for (int q = 0; q < 4; q++) acc[mt][nt][q] = 0.f;

    auto compute = [&](int buf) {
#pragma unroll
        for (int ks = 0; ks < 2; ks++) {
            uint32_t a[4][4];
#pragma unroll
            for (int mt = 0; mt < 4; mt++) {
                uint32_t addr = smem_u32(As[buf] + (wm * 64 + mt * 16 + a_row) * 40
                                                  + ks * 16 + a_koff);
                LDMX4(a[mt][0], a[mt][1], a[mt][2], a[mt][3], addr);
            }
#pragma unroll
            for (int nt2 = 0; nt2 < 2; nt2++) {
                uint32_t b[4];
                uint32_t addr = smem_u32(Bs[buf] + (wn * 32 + nt2 * 16 + b_row) * 40
                                                  + ks * 16 + b_koff);
                LDMX4(b[0], b[1], b[2], b[3], addr);
#pragma unroll
                for (int sub = 0; sub < 2; sub++)
#pragma unroll
                    for (int mt = 0; mt < 4; mt++)
                        mma16816(acc[mt][nt2 * 2 + sub], a[mt],
                                 b[sub * 2], b[sub * 2 + 1]);
            }
        }
    };

    loadAB(k0base);
    stsAB(0);
    __syncthreads();
    for (int ch = 0; ch < NCH; ch++) {
        if (ch + 1 < NCH) loadAB(k0base + (ch + 1) * 32);
        compute(ch & 1);
        if (ch + 1 < NCH) stsAB((ch + 1) & 1);
        __syncthreads();
    }

    // epilogue: half2 stores. c0:(g,2t) c1:(g,2t+1) c2:(g+8,2t) c3:(g+8,2t+1)
#pragma unroll
    for (int mt = 0; mt < 4; mt++) {
#pragma unroll
        for (int nt = 0; nt < 4; nt++) {
            int col = wn * 32 + nt * 8 + 2 * t;
            float bb0 = bias ? bias[col] : 0.f;
            float bb1 = bias ? bias[col + 1] : 0.f;
            int row = m0 + wm * 64 + mt * 16 + g;
            *(__half2*)(Cg + (size_t)row * FOUT + col) =
                __floats2half2_rn(acc[mt][nt][0] + bb0, acc[mt][nt][1] + bb1);
            *(__half2*)(Cg + (size_t)(row + 8) * FOUT + col) =
                __floats2half2_rn(acc[mt][nt][2] + bb0, acc[mt][nt][3] + bb1);
        }
    }
}

// ---------------------------------------------------------------------------
// K0a/K0b: weight transposes to half (unchanged, passing)
// ---------------------------------------------------------------------------
__global__ __launch_bounds__(256) void k_trWp(const float* __restrict__ Wp) {
    __shared__ float tb[32][33];
    const int k0 = blockIdx.x * 32, n0 = blockIdx.y * 32;
    const int tx = threadIdx.x & 31, ty0 = threadIdx.x >> 5;
#pragma unroll
    for (int dy = 0; dy < 32; dy += 8)
        tb[ty0 + dy][tx] = Wp[(size_t)(k0 + ty0 + dy) * FOUT + n0 + tx];
    __syncthreads();
#pragma unroll
    for (int dy = 0; dy < 32; dy += 8)
        g_WpTh[(size_t)(n0 + ty0 + dy) * FIN + k0 + tx] = __float2half_rn(tb[tx][ty0 + dy]);
}

__global__ __launch_bounds__(256) void k_trW1(const float* __restrict__ W1) {
    __shared__ float tb[32][33];
    const int z  = blockIdx.z;
    const int k0 = blockIdx.x * 32, f0 = blockIdx.y * 32;
    const int tx = threadIdx.x & 31, ty0 = threadIdx.x >> 5;
    const float* src = W1 + ((size_t)(z >> 1) * 2 * FOUT + (z & 1) * FOUT) * FOUT;
#pragma unroll
    for (int dy = 0; dy < 32; dy += 8)
        tb[ty0 + dy][tx] = src[(size_t)(k0 + ty0 + dy) * FOUT + f0 + tx];
    __syncthreads();
#pragma unroll
    for (int dy = 0; dy < 32; dy += 8)
        g_W1Th[z][(size_t)(f0 + ty0 + dy) * FOUT + k0 + tx] = __float2half_rn(tb[tx][ty0 + dy]);
}

// ---------------------------------------------------------------------------
// K1: split-K partials (half) of emb = x @ Wp
// ---------------------------------------------------------------------------
__global__ __launch_bounds__(256) void k_emb(const float* __restrict__ x) {
    gemm128h<KCHUNK / 32, false>(x, FIN, g_WpTh, FIN, blockIdx.y * KCHUNK,
                                 blockIdx.x * 128, nullptr, g_parth[blockIdx.y]);
}

// K1b: g_embh = half(sum of 8 half partials + bp); sums in fp32.
__global__ __launch_bounds__(256) void k_reduce8(const float* __restrict__ bp) {
    const int i = (blockIdx.x * 256 + threadIdx.x) * 8;   // half index
    float a[8];
#pragma unroll
    for (int j = 0; j < 8; j++) a[j] = 0.f;
#pragma unroll
    for (int p = 0; p < KSPLIT; p++) {
        uint4 v = *(const uint4*)(g_parth[p] + i);
        __half2* h = (__half2*)&v;
#pragma unroll
        for (int j = 0; j < 4; j++) {
            float2 f = __half22float2(h[j]);
            a[2 * j] += f.x; a[2 * j + 1] += f.y;
        }
    }
    const int cb = i & 127;
    uint4 o;
    __half2* oh = (__half2*)&o;
#pragma unroll
    for (int j = 0; j < 4; j++)
        oh[j] = __floats2half2_rn(a[2 * j] + bp[cb + 2 * j],
                                  a[2 * j + 1] + bp[cb + 2 * j + 1]);
    *(uint4*)(g_embh + i) = o;
}

// ---------------------------------------------------------------------------
// K2: g_ACh[z] = emb @ W1Th[z]^T  (+b1 on even z)   — all-half operand path
// ---------------------------------------------------------------------------
__global__ __launch_bounds__(256) void k_proj(const float* __restrict__ b1) {
    const int z = blockIdx.y;
    const float* bias = ((z & 1) == 0) ? (b1 + (size_t)(z >> 1) * FOUT) : nullptr;
    gemm128h<FOUT / 32, true>(g_embh, FOUT, g_W1Th[z], FOUT, 0,
                              blockIdx.x * 128, bias, g_ACh[z]);
}

// ---------------------------------------------------------------------------
// K3: pair scoring from half A/C: f-split 8 lanes/pair, 4 pairs/warp-iter.
// S(i,k) = sum_f leaky(A[i][f]+C[k][f])*W2[h][f] + b2[h]
// out[b,h,j,i] = S(i, j+(j>=i)) for j<9;  out[b,h,9,:] = 0
// ---------------------------------------------------------------------------
__global__ __launch_bounds__(128) void k_pair4(const float* __restrict__ W2,
                                               const float* __restrict__ b2,
                                               float* __restrict__ out) {
    __shared__ __align__(16) __half As[NNODES * 136];
    __shared__ __align__(16) __half Cs[NNODES * 136];
    const int b = blockIdx.x, h = blockIdx.y;
    const int tid = threadIdx.x, lane = tid & 31, warp = tid >> 5;

    const __half* Ap = g_ACh[2 * h]     + (size_t)b * NNODES * FOUT;
    const __half* Cp = g_ACh[2 * h + 1] + (size_t)b * NNODES * FOUT;
    for (int e = tid; e < NNODES * 16; e += 128) {
        int r = e >> 4, c8 = (e & 15) * 8;
        *(uint4*)(As + r * 136 + c8) = *(const uint4*)(Ap + r * FOUT + c8);
        *(uint4*)(Cs + r * 136 + c8) = *(const uint4*)(Cp + r * FOUT + c8);
    }
    const int sub = lane >> 3;       // pair-in-group 0..3
    const int fl  = lane & 7;        // f-slice 0..7 (16 cols each)
    float4 w2v[4];
#pragma unroll
    for (int j = 0; j < 4; j++) w2v[j] = *(const float4*)(W2 + h * FOUT + fl * 16 + j * 4);
    const float b2v = b2[h];
    __syncthreads();

    float* outp = out + ((size_t)b * NHEADS + h) * 100;
    for (int q = warp; q < 23; q += 4) {
        const int p = q * 4 + sub;
        float s = 0.f;
        int i = 0, kk = 0;
        if (p < 90) {
            i  = p / 9;
            kk = p - i * 9;
            const int k = kk + (kk >= i);
            const __half* ar = As + i * 136 + fl * 16;
            const __half* cr = Cs + k * 136 + fl * 16;
            uint4 ua0 = *(const uint4*)ar;
            uint4 ua1 = *(const uint4*)(ar + 8);
            uint4 uc0 = *(const uint4*)cr;
            uint4 uc1 = *(const uint4*)(cr + 8);
            float v[16];
            __half2* ha0 = (__half2*)&ua0; __half2* hc0 = (__half2*)&uc0;
            __half2* ha1 = (__half2*)&ua1; __half2* hc1 = (__half2*)&uc1;
#pragma unroll
            for (int jj = 0; jj < 4; jj++) {
                float2 fa = __half22float2(ha0[jj]);
                float2 fc = __half22float2(hc0[jj]);
                v[2 * jj]     = fa.x + fc.x;
                v[2 * jj + 1] = fa.y + fc.y;
                float2 fa1 = __half22float2(ha1[jj]);
                float2 fc1 = __half22float2(hc1[jj]);
                v[8 + 2 * jj]     = fa1.x + fc1.x;
                v[8 + 2 * jj + 1] = fa1.y + fc1.y;
            }
#pragma unroll
            for (int j = 0; j < 4; j++) {
                float v0 = v[4 * j], v1 = v[4 * j + 1], v2 = v[4 * j + 2], v3 = v[4 * j + 3];
                v0 = (v0 > 0.f) ? v0 : 0.2f * v0;
                v1 = (v1 > 0.f) ? v1 : 0.2f * v1;
                v2 = (v2 > 0.f) ? v2 : 0.2f * v2;
                v3 = (v3 > 0.f) ? v3 : 0.2f * v3;
                s += v0 * w2v[j].x + v1 * w2v[j].y + v2 * w2v[j].z + v3 * w2v[j].w;
            }
        }
        s += __shfl_xor_sync(0xffffffffu, s, 4);
        s += __shfl_xor_sync(0xffffffffu, s, 2);
        s += __shfl_xor_sync(0xffffffffu, s, 1);
        if (p < 90 && fl == 0) outp[kk * 10 + i] = s + b2v;
    }
    if (tid < 10) outp[90 + tid] = 0.f;
}

// ---------------------------------------------------------------------------
// Launch. inputs: 0 object_features, 1 scene_geometry(unused), 2 Wp, 3 bp,
//                 4 W1, 5 b1, 6 W2, 7 b2, 8 d_max
// ---------------------------------------------------------------------------
extern "C" void kernel_launch(void* const* d_in, const int* in_sizes, int n_in,
                              void* d_out, int out_size) {
    const float* x  = (const float*)d_in[0];
    const float* Wp = (const float*)d_in[2];
    const float* bp = (const float*)d_in[3];
    const float* W1 = (const float*)d_in[4];
    const float* b1 = (const float*)d_in[5];
    const float* W2 = (const float*)d_in[6];
    const float* b2 = (const float*)d_in[7];
    float* out = (float*)d_out;

    dim3 gtw(FIN / 32, FOUT / 32);
    k_trWp<<<gtw, 256>>>(Wp);
    dim3 gt1(FOUT / 32, FOUT / 32, 16);
    k_trW1<<<gt1, 256>>>(W1);

    dim3 g1(MTOT / 128, KSPLIT);
    k_emb<<<g1, 256>>>(x);

    k_reduce8<<<MTOT * FOUT / (256 * 8), 256>>>(bp);

    dim3 g2(MTOT / 128, 16);
    k_proj<<<g2, 256>>>(b1);

    dim3 g3(NB, NHEADS);
    k_pair4<<<g3, 128>>>(W2, b2, out);
}